// round 15
// baseline (speedup 1.0000x reference)
#include <cuda_runtime.h>
#include <cstdint>

#define KK   27
#define TPB  128
#define NPB  128            // nodes per block: 32 per warp, 4 warps

typedef unsigned long long ull;

// ---- packed f32x2 helpers ----
__device__ __forceinline__ ull splat2(float v) {
    ull r; asm("mov.b64 %0, {%1, %1};" : "=l"(r) : "f"(v)); return r;
}
__device__ __forceinline__ ull pack2(float lo, float hi) {
    ull r; asm("mov.b64 %0, {%1, %2};" : "=l"(r) : "f"(lo), "f"(hi)); return r;
}
__device__ __forceinline__ void ffma2(ull& d, ull a, ull b) {
    asm("fma.rn.f32x2 %0, %1, %2, %0;" : "+l"(d) : "l"(a), "l"(b));
}
__device__ __forceinline__ ull addp2(ull a, ull b) {
    ull r; asm("add.rn.f32x2 %0, %1, %2;" : "=l"(r) : "l"(a), "l"(b)); return r;
}
__device__ __forceinline__ float getf(const float4& v, int j) {
    switch (j) { case 0: return v.x; case 1: return v.y;
                 case 2: return v.z; default: return v.w; }
}
__device__ __forceinline__ int geti(const int4& v, int j) {
    switch (j) { case 0: return v.x; case 1: return v.y;
                 case 2: return v.z; default: return v.w; }
}

// Y[i][o] = bias[o] + sum_k sum_c X[nbr[i][k]][c] * W[k][c][o]
//
// Decomposition (R8-R14): lane l -> m = l&3 (channel-quad), h = (l>>2)&1
// (output-half), ns = l>>3 (node octet); lane holds partials over channels
// [4m,4m+4) x outputs [8h,8h+8) for 8 nodes. Conflict-free weight smem,
// __ldcg gather, WAR-recycled xc pipeline, 16 warps/SM (128-reg cap hard).
//
// R15: (1) per-row recycle - each xc[j]'s next-k gather issues immediately
// after row j's last FFMA (spreads the LDG burst among FFMAs, adds ~40 issue
// slots of lookahead for early rows); (2) peel k=26 (removes the redundant
// 28th gather round, ~3.5% of gather LSU, and the kn clamp).

__global__ __launch_bounds__(TPB, 4)
void conv_kernel(const float* __restrict__ x,       // [N_in, 16]
                 const float* __restrict__ w,       // [27, 16, 16]
                 const float* __restrict__ bias,    // [16]
                 const int*   __restrict__ nbr,     // [N_out, 27]
                 float*       __restrict__ out,     // [N_out, 16]
                 int n_out,
                 const int*   __restrict__ lvl,
                 long long tail_start, int tail_count)
{
    __shared__ __align__(16) float ws[KK * 256];    // 27648 B, permuted
    __shared__ __align__(16) int idxT[KK * NPB];    // 13824 B, [k][node]

    // tail passthrough for flattened (out, level) tuple
    if (blockIdx.x == 0 && lvl != nullptr)
        for (int i = threadIdx.x; i < tail_count; i += TPB)
            out[tail_start + i] = (float)(*lvl);

    // Stage weights permuted (conflict-free 16B-stride lane classes), float4:
    //   scalar map: i = k*256 + c*16 + o; jj=c&3, q=(c>>2)+4*(o>>3), e=o&7
    //   ws[k*256 + jj*64 + (e>>2)*32 + q*4 + (e&3)] = w[i]
    {
        const float4* w4 = reinterpret_cast<const float4*>(w);
        for (int i4 = threadIdx.x; i4 < KK * 64; i4 += TPB) {
            int k = i4 >> 6, rem = i4 & 63;
            int c = rem >> 2, o4 = rem & 3;
            float4 v = __ldg(&w4[i4]);
            int q = (c >> 2) + 4 * (o4 >> 1);
            int dst = k * 256 + (c & 3) * 64 + (o4 & 1) * 32 + q * 4;
            *reinterpret_cast<float4*>(ws + dst) = v;
        }
    }
    // Stage indices transposed: idxT[k][node_local] (coalesced gmem reads)
    const int base = blockIdx.x * NPB;
    for (int i = threadIdx.x; i < KK * NPB; i += TPB) {
        int nl = i / KK, kk = i - nl * KK;
        int node = base + nl;
        if (node >= n_out) node = n_out - 1;
        idxT[kk * NPB + nl] = __ldcg(&nbr[(long long)node * KK + kk]);
    }
    __syncthreads();

    const int warp = threadIdx.x >> 5;
    const int lane = threadIdx.x & 31;
    const int warpbase = base + warp * 32;
    if (warpbase >= n_out) return;
    const int m  = lane & 3;
    const int h  = (lane >> 2) & 1;
    const int ns = lane >> 3;
    const int nlb = warp * 32 + ns * 8;             // local node base (8)
    const int q4 = (m + 4 * h) * 4;                 // lane-class float offset

    ull acc[8][4];                                   // [node][out-pair]
#pragma unroll
    for (int j = 0; j < 8; ++j)
#pragma unroll
        for (int p = 0; p < 4; ++p) acc[j][p] = 0ull;

    // preload k=0: all 8 rows
    float4 xc[8];
    {
        int4 ia = *reinterpret_cast<const int4*>(idxT + nlb);
        int4 ib = *reinterpret_cast<const int4*>(idxT + nlb + 4);
#pragma unroll
        for (int j = 0; j < 4; ++j)
            xc[j] = __ldcg(reinterpret_cast<const float4*>(
                               x + (size_t)geti(ia, j) * 16) + m);
#pragma unroll
        for (int j = 0; j < 4; ++j)
            xc[4 + j] = __ldcg(reinterpret_cast<const float4*>(
                                   x + (size_t)geti(ib, j) * 16) + m);
    }

#pragma unroll 1
    for (int k = 0; k < KK - 1; ++k) {
        const float* wk = ws + k * 256 + q4;
        const int knb = (k + 1) * NPB + nlb;

        // idx for next-k rows 0-3 (LDS latency covered by phase 1)
        int4 ia = *reinterpret_cast<const int4*>(idxT + knb);

        // phase 1: rows 0-3 x channels jj=0,1
        {
            ulonglong2 wA0 = *reinterpret_cast<const ulonglong2*>(wk);
            ulonglong2 wB0 = *reinterpret_cast<const ulonglong2*>(wk + 32);
            ulonglong2 wA1 = *reinterpret_cast<const ulonglong2*>(wk + 64);
            ulonglong2 wB1 = *reinterpret_cast<const ulonglong2*>(wk + 96);
#pragma unroll
            for (int j = 0; j < 4; ++j) {
                const ull a0 = splat2(getf(xc[j], 0));
                ffma2(acc[j][0], a0, wA0.x);
                ffma2(acc[j][1], a0, wA0.y);
                ffma2(acc[j][2], a0, wB0.x);
                ffma2(acc[j][3], a0, wB0.y);
                const ull a1 = splat2(getf(xc[j], 1));
                ffma2(acc[j][0], a1, wA1.x);
                ffma2(acc[j][1], a1, wA1.y);
                ffma2(acc[j][2], a1, wB1.x);
                ffma2(acc[j][3], a1, wB1.y);
            }
        }
        // phase 2: rows 0-3 x channels jj=2,3; per-row WAR recycle:
        // xc[j] overwritten with next-k gather right after its last FFMA
        ulonglong2 wA3 = *reinterpret_cast<const ulonglong2*>(wk + 192);
        ulonglong2 wB3 = *reinterpret_cast<const ulonglong2*>(wk + 224);
        {
            ulonglong2 wA2 = *reinterpret_cast<const ulonglong2*>(wk + 128);
            ulonglong2 wB2 = *reinterpret_cast<const ulonglong2*>(wk + 160);
#pragma unroll
            for (int j = 0; j < 4; ++j) {
                const ull a2 = splat2(getf(xc[j], 2));
                ffma2(acc[j][0], a2, wA2.x);
                ffma2(acc[j][1], a2, wA2.y);
                ffma2(acc[j][2], a2, wB2.x);
                ffma2(acc[j][3], a2, wB2.y);
                const ull a3 = splat2(getf(xc[j], 3));
                ffma2(acc[j][0], a3, wA3.x);
                ffma2(acc[j][1], a3, wA3.y);
                ffma2(acc[j][2], a3, wB3.x);
                ffma2(acc[j][3], a3, wB3.y);
                xc[j] = __ldcg(reinterpret_cast<const float4*>(
                                   x + (size_t)geti(ia, j) * 16) + m);
            }
        }

        // idx for next-k rows 4-7
        int4 ib = *reinterpret_cast<const int4*>(idxT + knb + 4);

        // phase 3: rows 4-7 x channels jj=0,1 (reload jj01 quads)
        {
            ulonglong2 wA0 = *reinterpret_cast<const ulonglong2*>(wk);
            ulonglong2 wB0 = *reinterpret_cast<const ulonglong2*>(wk + 32);
            ulonglong2 wA1 = *reinterpret_cast<const ulonglong2*>(wk + 64);
            ulonglong2 wB1 = *reinterpret_cast<const ulonglong2*>(wk + 96);
#pragma unroll
            for (int j = 4; j < 8; ++j) {
                const ull a0 = splat2(getf(xc[j], 0));
                ffma2(acc[j][0], a0, wA0.x);
                ffma2(acc[j][1], a0, wA0.y);
                ffma2(acc[j][2], a0, wB0.x);
                ffma2(acc[j][3], a0, wB0.y);
                const ull a1 = splat2(getf(xc[j], 1));
                ffma2(acc[j][0], a1, wA1.x);
                ffma2(acc[j][1], a1, wA1.y);
                ffma2(acc[j][2], a1, wB1.x);
                ffma2(acc[j][3], a1, wB1.y);
            }
        }
        // phase 4: rows 4-7 x channels jj=2,3; per-row recycle
        {
            ulonglong2 wA2 = *reinterpret_cast<const ulonglong2*>(wk + 128);
            ulonglong2 wB2 = *reinterpret_cast<const ulonglong2*>(wk + 160);
#pragma unroll
            for (int j = 4; j < 8; ++j) {
                const ull a2 = splat2(getf(xc[j], 2));
                ffma2(acc[j][0], a2, wA2.x);
                ffma2(acc[j][1], a2, wA2.y);
                ffma2(acc[j][2], a2, wB2.x);
                ffma2(acc[j][3], a2, wB2.y);
                const ull a3 = splat2(getf(xc[j], 3));
                ffma2(acc[j][0], a3, wA3.x);
                ffma2(acc[j][1], a3, wA3.y);
                ffma2(acc[j][2], a3, wB3.x);
                ffma2(acc[j][3], a3, wB3.y);
                xc[j] = __ldcg(reinterpret_cast<const float4*>(
                                   x + (size_t)geti(ib, j - 4) * 16) + m);
            }
        }
    }

    // peeled final k = KK-1: no gathers
    {
        const float* wk = ws + (KK - 1) * 256 + q4;
        ulonglong2 wA0 = *reinterpret_cast<const ulonglong2*>(wk);
        ulonglong2 wB0 = *reinterpret_cast<const ulonglong2*>(wk + 32);
        ulonglong2 wA1 = *reinterpret_cast<const ulonglong2*>(wk + 64);
        ulonglong2 wB1 = *reinterpret_cast<const ulonglong2*>(wk + 96);
        ulonglong2 wA2 = *reinterpret_cast<const ulonglong2*>(wk + 128);
        ulonglong2 wB2 = *reinterpret_cast<const ulonglong2*>(wk + 160);
        ulonglong2 wA3 = *reinterpret_cast<const ulonglong2*>(wk + 192);
        ulonglong2 wB3 = *reinterpret_cast<const ulonglong2*>(wk + 224);
#pragma unroll
        for (int j = 0; j < 8; ++j) {
            const ull a0 = splat2(getf(xc[j], 0));
            ffma2(acc[j][0], a0, wA0.x);
            ffma2(acc[j][1], a0, wA0.y);
            ffma2(acc[j][2], a0, wB0.x);
            ffma2(acc[j][3], a0, wB0.y);
            const ull a1 = splat2(getf(xc[j], 1));
            ffma2(acc[j][0], a1, wA1.x);
            ffma2(acc[j][1], a1, wA1.y);
            ffma2(acc[j][2], a1, wB1.x);
            ffma2(acc[j][3], a1, wB1.y);
            const ull a2 = splat2(getf(xc[j], 2));
            ffma2(acc[j][0], a2, wA2.x);
            ffma2(acc[j][1], a2, wA2.y);
            ffma2(acc[j][2], a2, wB2.x);
            ffma2(acc[j][3], a2, wB2.y);
            const ull a3 = splat2(getf(xc[j], 3));
            ffma2(acc[j][0], a3, wA3.x);
            ffma2(acc[j][1], a3, wA3.y);
            ffma2(acc[j][2], a3, wB3.x);
            ffma2(acc[j][3], a3, wB3.y);
        }
    }

    // Epilogue: reduce channel-quad partials over the 4 m-lanes, add bias.
    float4 b0 = __ldg(reinterpret_cast<const float4*>(bias) + 2 * h);
    float4 b1 = __ldg(reinterpret_cast<const float4*>(bias) + 2 * h + 1);
    ull bp[4] = { pack2(b0.x, b0.y), pack2(b0.z, b0.w),
                  pack2(b1.x, b1.y), pack2(b1.z, b1.w) };

#pragma unroll
    for (int j = 0; j < 8; ++j) {
#pragma unroll
        for (int p = 0; p < 4; ++p) {
            ull v = acc[j][p];
            v = addp2(v, __shfl_xor_sync(0xffffffffu, v, 1));
            v = addp2(v, __shfl_xor_sync(0xffffffffu, v, 2));
            acc[j][p] = v;
        }
        const int node = warpbase + ns * 8 + j;
        if (m == 0 && node < n_out) {
            ulonglong2* op = reinterpret_cast<ulonglong2*>(
                out + (long long)node * 16 + 8 * h);
            ulonglong2 s0; s0.x = addp2(acc[j][0], bp[0]);
                           s0.y = addp2(acc[j][1], bp[1]);
            ulonglong2 s1; s1.x = addp2(acc[j][2], bp[2]);
                           s1.y = addp2(acc[j][3], bp[3]);
            op[0] = s0;
            op[1] = s1;
        }
    }
}

extern "C" void kernel_launch(void* const* d_in, const int* in_sizes, int n_in,
                              void* d_out, int out_size)
{
    const float* x    = (const float*)d_in[0];
    const float* w    = (const float*)d_in[1];
    const float* bias = (const float*)d_in[2];
    const int*   nbr  = (const int*)d_in[3];
    const int*   lvl  = (n_in > 4) ? (const int*)d_in[4] : nullptr;

    const int n_out = in_sizes[3] / KK;
    float* out = (float*)d_out;

    const long long conv_elems = (long long)n_out * 16;
    long long tail_start = conv_elems;
    int tail_count = 0;
    if ((long long)out_size > conv_elems && lvl != nullptr)
        tail_count = (int)((long long)out_size - conv_elems);

    const int grid = (n_out + NPB - 1) / NPB;
    conv_kernel<<<grid, TPB>>>(x, w, bias, nbr, out, n_out,
                               lvl, tail_start, tail_count);
}

// round 16
// speedup vs baseline: 1.0823x; 1.0823x over previous
#include <cuda_runtime.h>
#include <cstdint>

#define KK   27
#define TPB  128
#define NPB  128            // nodes per block: 32 per warp, 4 warps

typedef unsigned long long ull;

// ---- packed f32x2 helpers ----
__device__ __forceinline__ ull splat2(float v) {
    ull r; asm("mov.b64 %0, {%1, %1};" : "=l"(r) : "f"(v)); return r;
}
__device__ __forceinline__ ull pack2(float lo, float hi) {
    ull r; asm("mov.b64 %0, {%1, %2};" : "=l"(r) : "f"(lo), "f"(hi)); return r;
}
__device__ __forceinline__ void ffma2(ull& d, ull a, ull b) {
    asm("fma.rn.f32x2 %0, %1, %2, %0;" : "+l"(d) : "l"(a), "l"(b));
}
__device__ __forceinline__ ull addp2(ull a, ull b) {
    ull r; asm("add.rn.f32x2 %0, %1, %2;" : "=l"(r) : "l"(a), "l"(b)); return r;
}
__device__ __forceinline__ float getf(const float4& v, int j) {
    switch (j) { case 0: return v.x; case 1: return v.y;
                 case 2: return v.z; default: return v.w; }
}

// Y[i][o] = bias[o] + sum_k sum_c X[nbr[i][k]][c] * W[k][c][o]
//
// Decomposition (R8-R14): lane l -> m = l&3 (channel-quad), h = (l>>2)&1
// (output-half), ns = l>>3 (node octet); lane holds partials over channels
// [4m,4m+4) x outputs [8h,8h+8) for 8 nodes. Conflict-free weight smem,
// __ldcg gather, 16 warps/SM (128-reg cap hard; R11/R15 proved spills).
//
// R16 = R14 (batch WAR-recycle after phase 2 / phase 4 — the schedule that
// compiles to 126 regs) + peel of k=26 only: mainloop runs 26 iters, final k
// consumes xc without the redundant 28th gather round (R15's per-row recycle
// is reverted; it pushed pressure to 128 regs and spilled, L2 22->37%).

__global__ __launch_bounds__(TPB, 4)
void conv_kernel(const float* __restrict__ x,       // [N_in, 16]
                 const float* __restrict__ w,       // [27, 16, 16]
                 const float* __restrict__ bias,    // [16]
                 const int*   __restrict__ nbr,     // [N_out, 27]
                 float*       __restrict__ out,     // [N_out, 16]
                 int n_out,
                 const int*   __restrict__ lvl,
                 long long tail_start, int tail_count)
{
    __shared__ __align__(16) float ws[KK * 256];    // 27648 B, permuted
    __shared__ __align__(16) int idxT[KK * NPB];    // 13824 B, [k][node]

    // tail passthrough for flattened (out, level) tuple
    if (blockIdx.x == 0 && lvl != nullptr)
        for (int i = threadIdx.x; i < tail_count; i += TPB)
            out[tail_start + i] = (float)(*lvl);

    // Stage weights permuted (conflict-free 16B-stride lane classes), float4:
    //   scalar map: i = k*256 + c*16 + o; jj=c&3, q=(c>>2)+4*(o>>3), e=o&7
    //   ws[k*256 + jj*64 + (e>>2)*32 + q*4 + (e&3)] = w[i]
    {
        const float4* w4 = reinterpret_cast<const float4*>(w);
        for (int i4 = threadIdx.x; i4 < KK * 64; i4 += TPB) {
            int k = i4 >> 6, rem = i4 & 63;
            int c = rem >> 2, o4 = rem & 3;
            float4 v = __ldg(&w4[i4]);
            int q = (c >> 2) + 4 * (o4 >> 1);
            int dst = k * 256 + (c & 3) * 64 + (o4 & 1) * 32 + q * 4;
            *reinterpret_cast<float4*>(ws + dst) = v;
        }
    }
    // Stage indices transposed: idxT[k][node_local] (coalesced gmem reads)
    const int base = blockIdx.x * NPB;
    for (int i = threadIdx.x; i < KK * NPB; i += TPB) {
        int nl = i / KK, kk = i - nl * KK;
        int node = base + nl;
        if (node >= n_out) node = n_out - 1;
        idxT[kk * NPB + nl] = __ldcg(&nbr[(long long)node * KK + kk]);
    }
    __syncthreads();

    const int warp = threadIdx.x >> 5;
    const int lane = threadIdx.x & 31;
    const int warpbase = base + warp * 32;
    if (warpbase >= n_out) return;
    const int m  = lane & 3;
    const int h  = (lane >> 2) & 1;
    const int ns = lane >> 3;
    const int nlb = warp * 32 + ns * 8;             // local node base (8)
    const int q4 = (m + 4 * h) * 4;                 // lane-class float offset

    ull acc[8][4];                                   // [node][out-pair]
#pragma unroll
    for (int j = 0; j < 8; ++j)
#pragma unroll
        for (int p = 0; p < 4; ++p) acc[j][p] = 0ull;

    // preload k=0: all 8 rows
    float4 xc[8];
    {
        int4 ia = *reinterpret_cast<const int4*>(idxT + nlb);
        int4 ib = *reinterpret_cast<const int4*>(idxT + nlb + 4);
        xc[0] = __ldcg(reinterpret_cast<const float4*>(x + (size_t)ia.x * 16) + m);
        xc[1] = __ldcg(reinterpret_cast<const float4*>(x + (size_t)ia.y * 16) + m);
        xc[2] = __ldcg(reinterpret_cast<const float4*>(x + (size_t)ia.z * 16) + m);
        xc[3] = __ldcg(reinterpret_cast<const float4*>(x + (size_t)ia.w * 16) + m);
        xc[4] = __ldcg(reinterpret_cast<const float4*>(x + (size_t)ib.x * 16) + m);
        xc[5] = __ldcg(reinterpret_cast<const float4*>(x + (size_t)ib.y * 16) + m);
        xc[6] = __ldcg(reinterpret_cast<const float4*>(x + (size_t)ib.z * 16) + m);
        xc[7] = __ldcg(reinterpret_cast<const float4*>(x + (size_t)ib.w * 16) + m);
    }

#pragma unroll 1
    for (int k = 0; k < KK - 1; ++k) {
        const float* wk = ws + k * 256 + q4;
        const int knb = (k + 1) * NPB + nlb;

        // idx for next-k rows 0-3 (29-cyc LDS latency covered by phase 1-2)
        int4 ia = *reinterpret_cast<const int4*>(idxT + knb);

        // phase 1: rows 0-3 x channels jj=0,1
        {
            ulonglong2 wA0 = *reinterpret_cast<const ulonglong2*>(wk);
            ulonglong2 wB0 = *reinterpret_cast<const ulonglong2*>(wk + 32);
            ulonglong2 wA1 = *reinterpret_cast<const ulonglong2*>(wk + 64);
            ulonglong2 wB1 = *reinterpret_cast<const ulonglong2*>(wk + 96);
#pragma unroll
            for (int j = 0; j < 4; ++j) {
                const ull a0 = splat2(getf(xc[j], 0));
                ffma2(acc[j][0], a0, wA0.x);
                ffma2(acc[j][1], a0, wA0.y);
                ffma2(acc[j][2], a0, wB0.x);
                ffma2(acc[j][3], a0, wB0.y);
                const ull a1 = splat2(getf(xc[j], 1));
                ffma2(acc[j][0], a1, wA1.x);
                ffma2(acc[j][1], a1, wA1.y);
                ffma2(acc[j][2], a1, wB1.x);
                ffma2(acc[j][3], a1, wB1.y);
            }
        }
        // phase 2: rows 0-3 x channels jj=2,3 (only wA3/wB3 stay persistent)
        ulonglong2 wA3 = *reinterpret_cast<const ulonglong2*>(wk + 192);
        ulonglong2 wB3 = *reinterpret_cast<const ulonglong2*>(wk + 224);
        {
            ulonglong2 wA2 = *reinterpret_cast<const ulonglong2*>(wk + 128);
            ulonglong2 wB2 = *reinterpret_cast<const ulonglong2*>(wk + 160);
#pragma unroll
            for (int j = 0; j < 4; ++j) {
                const ull a2 = splat2(getf(xc[j], 2));
                ffma2(acc[j][0], a2, wA2.x);
                ffma2(acc[j][1], a2, wA2.y);
                ffma2(acc[j][2], a2, wB2.x);
                ffma2(acc[j][3], a2, wB2.y);
                const ull a3 = splat2(getf(xc[j], 3));
                ffma2(acc[j][0], a3, wA3.x);
                ffma2(acc[j][1], a3, wA3.y);
                ffma2(acc[j][2], a3, wB3.x);
                ffma2(acc[j][3], a3, wB3.y);
            }
        }

        // rows 0-3 of k fully consumed -> recycle regs with next-k gather
        xc[0] = __ldcg(reinterpret_cast<const float4*>(x + (size_t)ia.x * 16) + m);
        xc[1] = __ldcg(reinterpret_cast<const float4*>(x + (size_t)ia.y * 16) + m);
        xc[2] = __ldcg(reinterpret_cast<const float4*>(x + (size_t)ia.z * 16) + m);
        xc[3] = __ldcg(reinterpret_cast<const float4*>(x + (size_t)ia.w * 16) + m);

        // idx for next-k rows 4-7
        int4 ib = *reinterpret_cast<const int4*>(idxT + knb + 4);

        // phase 3: rows 4-7 x channels jj=0,1 (reload jj01 quads)
        {
            ulonglong2 wA0 = *reinterpret_cast<const ulonglong2*>(wk);
            ulonglong2 wB0 = *reinterpret_cast<const ulonglong2*>(wk + 32);
            ulonglong2 wA1 = *reinterpret_cast<const ulonglong2*>(wk + 64);
            ulonglong2 wB1 = *reinterpret_cast<const ulonglong2*>(wk + 96);
#pragma unroll
            for (int j = 4; j < 8; ++j) {
                const ull a0 = splat2(getf(xc[j], 0));
                ffma2(acc[j][0], a0, wA0.x);
                ffma2(acc[j][1], a0, wA0.y);
                ffma2(acc[j][2], a0, wB0.x);
                ffma2(acc[j][3], a0, wB0.y);
                const ull a1 = splat2(getf(xc[j], 1));
                ffma2(acc[j][0], a1, wA1.x);
                ffma2(acc[j][1], a1, wA1.y);
                ffma2(acc[j][2], a1, wB1.x);
                ffma2(acc[j][3], a1, wB1.y);
            }
        }
        // phase 4: rows 4-7 x channels jj=2,3 (reload wA2/wB2; wA3/wB3 live)
        {
            ulonglong2 wA2 = *reinterpret_cast<const ulonglong2*>(wk + 128);
            ulonglong2 wB2 = *reinterpret_cast<const ulonglong2*>(wk + 160);
#pragma unroll
            for (int j = 4; j < 8; ++j) {
                const ull a2 = splat2(getf(xc[j], 2));
                ffma2(acc[j][0], a2, wA2.x);
                ffma2(acc[j][1], a2, wA2.y);
                ffma2(acc[j][2], a2, wB2.x);
                ffma2(acc[j][3], a2, wB2.y);
                const ull a3 = splat2(getf(xc[j], 3));
                ffma2(acc[j][0], a3, wA3.x);
                ffma2(acc[j][1], a3, wA3.y);
                ffma2(acc[j][2], a3, wB3.x);
                ffma2(acc[j][3], a3, wB3.y);
            }
        }

        // rows 4-7 consumed -> recycle with next-k gather
        xc[4] = __ldcg(reinterpret_cast<const float4*>(x + (size_t)ib.x * 16) + m);
        xc[5] = __ldcg(reinterpret_cast<const float4*>(x + (size_t)ib.y * 16) + m);
        xc[6] = __ldcg(reinterpret_cast<const float4*>(x + (size_t)ib.z * 16) + m);
        xc[7] = __ldcg(reinterpret_cast<const float4*>(x + (size_t)ib.w * 16) + m);
    }

    // peeled final k = KK-1: consume xc, no gathers, no idx loads
    {
        const float* wk = ws + (KK - 1) * 256 + q4;
        {
            ulonglong2 wA0 = *reinterpret_cast<const ulonglong2*>(wk);
            ulonglong2 wB0 = *reinterpret_cast<const ulonglong2*>(wk + 32);
            ulonglong2 wA1 = *reinterpret_cast<const ulonglong2*>(wk + 64);
            ulonglong2 wB1 = *reinterpret_cast<const ulonglong2*>(wk + 96);
#pragma unroll
            for (int j = 0; j < 8; ++j) {
                const ull a0 = splat2(getf(xc[j], 0));
                ffma2(acc[j][0], a0, wA0.x);
                ffma2(acc[j][1], a0, wA0.y);
                ffma2(acc[j][2], a0, wB0.x);
                ffma2(acc[j][3], a0, wB0.y);
                const ull a1 = splat2(getf(xc[j], 1));
                ffma2(acc[j][0], a1, wA1.x);
                ffma2(acc[j][1], a1, wA1.y);
                ffma2(acc[j][2], a1, wB1.x);
                ffma2(acc[j][3], a1, wB1.y);
            }
        }
        {
            ulonglong2 wA2 = *reinterpret_cast<const ulonglong2*>(wk + 128);
            ulonglong2 wB2 = *reinterpret_cast<const ulonglong2*>(wk + 160);
            ulonglong2 wA3 = *reinterpret_cast<const ulonglong2*>(wk + 192);
            ulonglong2 wB3 = *reinterpret_cast<const ulonglong2*>(wk + 224);
#pragma unroll
            for (int j = 0; j < 8; ++j) {
                const ull a2 = splat2(getf(xc[j], 2));
                ffma2(acc[j][0], a2, wA2.x);
                ffma2(acc[j][1], a2, wA2.y);
                ffma2(acc[j][2], a2, wB2.x);
                ffma2(acc[j][3], a2, wB2.y);
                const ull a3 = splat2(getf(xc[j], 3));
                ffma2(acc[j][0], a3, wA3.x);
                ffma2(acc[j][1], a3, wA3.y);
                ffma2(acc[j][2], a3, wB3.x);
                ffma2(acc[j][3], a3, wB3.y);
            }
        }
    }

    // Epilogue: reduce channel-quad partials over the 4 m-lanes, add bias.
    float4 b0 = __ldg(reinterpret_cast<const float4*>(bias) + 2 * h);
    float4 b1 = __ldg(reinterpret_cast<const float4*>(bias) + 2 * h + 1);
    ull bp[4] = { pack2(b0.x, b0.y), pack2(b0.z, b0.w),
                  pack2(b1.x, b1.y), pack2(b1.z, b1.w) };

#pragma unroll
    for (int j = 0; j < 8; ++j) {
#pragma unroll
        for (int p = 0; p < 4; ++p) {
            ull v = acc[j][p];
            v = addp2(v, __shfl_xor_sync(0xffffffffu, v, 1));
            v = addp2(v, __shfl_xor_sync(0xffffffffu, v, 2));
            acc[j][p] = v;
        }
        const int node = warpbase + ns * 8 + j;
        if (m == 0 && node < n_out) {
            ulonglong2* op = reinterpret_cast<ulonglong2*>(
                out + (long long)node * 16 + 8 * h);
            ulonglong2 s0; s0.x = addp2(acc[j][0], bp[0]);
                           s0.y = addp2(acc[j][1], bp[1]);
            ulonglong2 s1; s1.x = addp2(acc[j][2], bp[2]);
                           s1.y = addp2(acc[j][3], bp[3]);
            op[0] = s0;
            op[1] = s1;
        }
    }
}

extern "C" void kernel_launch(void* const* d_in, const int* in_sizes, int n_in,
                              void* d_out, int out_size)
{
    const float* x    = (const float*)d_in[0];
    const float* w    = (const float*)d_in[1];
    const float* bias = (const float*)d_in[2];
    const int*   nbr  = (const int*)d_in[3];
    const int*   lvl  = (n_in > 4) ? (const int*)d_in[4] : nullptr;

    const int n_out = in_sizes[3] / KK;
    float* out = (float*)d_out;

    const long long conv_elems = (long long)n_out * 16;
    long long tail_start = conv_elems;
    int tail_count = 0;
    if ((long long)out_size > conv_elems && lvl != nullptr)
        tail_count = (int)((long long)out_size - conv_elems);

    const int grid = (n_out + NPB - 1) / NPB;
    conv_kernel<<<grid, TPB>>>(x, w, bias, nbr, out, n_out,
                               lvl, tail_start, tail_count);
}

// round 17
// speedup vs baseline: 1.1546x; 1.0668x over previous
#include <cuda_runtime.h>
#include <cstdint>

#define KK   27
#define TPB  128
#define NPB  128            // nodes per block: 32 per warp, 4 warps

typedef unsigned long long ull;

// ---- packed f32x2 helpers ----
__device__ __forceinline__ ull splat2(float v) {
    ull r; asm("mov.b64 %0, {%1, %1};" : "=l"(r) : "f"(v)); return r;
}
__device__ __forceinline__ ull pack2(float lo, float hi) {
    ull r; asm("mov.b64 %0, {%1, %2};" : "=l"(r) : "f"(lo), "f"(hi)); return r;
}
__device__ __forceinline__ void ffma2(ull& d, ull a, ull b) {
    asm("fma.rn.f32x2 %0, %1, %2, %0;" : "+l"(d) : "l"(a), "l"(b));
}
__device__ __forceinline__ ull addp2(ull a, ull b) {
    ull r; asm("add.rn.f32x2 %0, %1, %2;" : "=l"(r) : "l"(a), "l"(b)); return r;
}
__device__ __forceinline__ float getf(const float4& v, int j) {
    switch (j) { case 0: return v.x; case 1: return v.y;
                 case 2: return v.z; default: return v.w; }
}

// Y[i][o] = bias[o] + sum_k sum_c X[nbr[i][k]][c] * W[k][c][o]
//
// Decomposition (R8-R10): lane l -> m = l&3 (channel-quad), h = (l>>2)&1
// (output-half), ns = l>>3 (node octet); lane holds partials over channels
// [4m,4m+4) x outputs [8h,8h+8) for 8 nodes. Conflict-free weight smem,
// __ldcg gather.
//
// R17 = exact R14 (the session optimum, 187.1us / 126 regs): WAR-recycling
// pipeline (xc halves overwritten with next-k gathers right after last read)
// at 16 warps/SM via launch_bounds(128,4). Phase 4 reloads wA2/wB2 from
// smem; only wA3/wB3 persist across phases 2->4. All structural variants
// (per-row recycle, k=26 peel, other block shapes, tighter reg caps) pushed
// ptxas past the 128-reg cliff and regressed (R11/R15/R16).

__global__ __launch_bounds__(TPB, 4)
void conv_kernel(const float* __restrict__ x,       // [N_in, 16]
                 const float* __restrict__ w,       // [27, 16, 16]
                 const float* __restrict__ bias,    // [16]
                 const int*   __restrict__ nbr,     // [N_out, 27]
                 float*       __restrict__ out,     // [N_out, 16]
                 int n_out,
                 const int*   __restrict__ lvl,
                 long long tail_start, int tail_count)
{
    __shared__ __align__(16) float ws[KK * 256];    // 27648 B, permuted
    __shared__ __align__(16) int idxT[KK * NPB];    // 13824 B, [k][node]

    // tail passthrough for flattened (out, level) tuple
    if (blockIdx.x == 0 && lvl != nullptr)
        for (int i = threadIdx.x; i < tail_count; i += TPB)
            out[tail_start + i] = (float)(*lvl);

    // Stage weights permuted (conflict-free 16B-stride lane classes), float4:
    //   scalar map: i = k*256 + c*16 + o; jj=c&3, q=(c>>2)+4*(o>>3), e=o&7
    //   ws[k*256 + jj*64 + (e>>2)*32 + q*4 + (e&3)] = w[i]
    {
        const float4* w4 = reinterpret_cast<const float4*>(w);
        for (int i4 = threadIdx.x; i4 < KK * 64; i4 += TPB) {
            int k = i4 >> 6, rem = i4 & 63;
            int c = rem >> 2, o4 = rem & 3;
            float4 v = __ldg(&w4[i4]);
            int q = (c >> 2) + 4 * (o4 >> 1);
            int dst = k * 256 + (c & 3) * 64 + (o4 & 1) * 32 + q * 4;
            *reinterpret_cast<float4*>(ws + dst) = v;
        }
    }
    // Stage indices transposed: idxT[k][node_local] (coalesced gmem reads)
    const int base = blockIdx.x * NPB;
    for (int i = threadIdx.x; i < KK * NPB; i += TPB) {
        int nl = i / KK, kk = i - nl * KK;
        int node = base + nl;
        if (node >= n_out) node = n_out - 1;
        idxT[kk * NPB + nl] = __ldcg(&nbr[(long long)node * KK + kk]);
    }
    __syncthreads();

    const int warp = threadIdx.x >> 5;
    const int lane = threadIdx.x & 31;
    const int warpbase = base + warp * 32;
    if (warpbase >= n_out) return;
    const int m  = lane & 3;
    const int h  = (lane >> 2) & 1;
    const int ns = lane >> 3;
    const int nlb = warp * 32 + ns * 8;             // local node base (8)
    const int q4 = (m + 4 * h) * 4;                 // lane-class float offset

    ull acc[8][4];                                   // [node][out-pair]
#pragma unroll
    for (int j = 0; j < 8; ++j)
#pragma unroll
        for (int p = 0; p < 4; ++p) acc[j][p] = 0ull;

    // preload k=0: all 8 rows
    float4 xc[8];
    {
        int4 ia = *reinterpret_cast<const int4*>(idxT + nlb);
        int4 ib = *reinterpret_cast<const int4*>(idxT + nlb + 4);
        xc[0] = __ldcg(reinterpret_cast<const float4*>(x + (size_t)ia.x * 16) + m);
        xc[1] = __ldcg(reinterpret_cast<const float4*>(x + (size_t)ia.y * 16) + m);
        xc[2] = __ldcg(reinterpret_cast<const float4*>(x + (size_t)ia.z * 16) + m);
        xc[3] = __ldcg(reinterpret_cast<const float4*>(x + (size_t)ia.w * 16) + m);
        xc[4] = __ldcg(reinterpret_cast<const float4*>(x + (size_t)ib.x * 16) + m);
        xc[5] = __ldcg(reinterpret_cast<const float4*>(x + (size_t)ib.y * 16) + m);
        xc[6] = __ldcg(reinterpret_cast<const float4*>(x + (size_t)ib.z * 16) + m);
        xc[7] = __ldcg(reinterpret_cast<const float4*>(x + (size_t)ib.w * 16) + m);
    }

#pragma unroll 1
    for (int k = 0; k < KK; ++k) {
        const int kn = (k + 1 < KK) ? (k + 1) : (KK - 1);
        const float* wk = ws + k * 256 + q4;

        // idx for next-k rows 0-3 (29-cyc LDS latency covered by phase 1-2)
        int4 ia = *reinterpret_cast<const int4*>(idxT + kn * NPB + nlb);

        // phase 1: rows 0-3 x channels jj=0,1
        {
            ulonglong2 wA0 = *reinterpret_cast<const ulonglong2*>(wk);
            ulonglong2 wB0 = *reinterpret_cast<const ulonglong2*>(wk + 32);
            ulonglong2 wA1 = *reinterpret_cast<const ulonglong2*>(wk + 64);
            ulonglong2 wB1 = *reinterpret_cast<const ulonglong2*>(wk + 96);
#pragma unroll
            for (int j = 0; j < 4; ++j) {
                const ull a0 = splat2(getf(xc[j], 0));
                ffma2(acc[j][0], a0, wA0.x);
                ffma2(acc[j][1], a0, wA0.y);
                ffma2(acc[j][2], a0, wB0.x);
                ffma2(acc[j][3], a0, wB0.y);
                const ull a1 = splat2(getf(xc[j], 1));
                ffma2(acc[j][0], a1, wA1.x);
                ffma2(acc[j][1], a1, wA1.y);
                ffma2(acc[j][2], a1, wB1.x);
                ffma2(acc[j][3], a1, wB1.y);
            }
        }
        // phase 2: rows 0-3 x channels jj=2,3 (only wA3/wB3 stay persistent)
        ulonglong2 wA3 = *reinterpret_cast<const ulonglong2*>(wk + 192);
        ulonglong2 wB3 = *reinterpret_cast<const ulonglong2*>(wk + 224);
        {
            ulonglong2 wA2 = *reinterpret_cast<const ulonglong2*>(wk + 128);
            ulonglong2 wB2 = *reinterpret_cast<const ulonglong2*>(wk + 160);
#pragma unroll
            for (int j = 0; j < 4; ++j) {
                const ull a2 = splat2(getf(xc[j], 2));
                ffma2(acc[j][0], a2, wA2.x);
                ffma2(acc[j][1], a2, wA2.y);
                ffma2(acc[j][2], a2, wB2.x);
                ffma2(acc[j][3], a2, wB2.y);
                const ull a3 = splat2(getf(xc[j], 3));
                ffma2(acc[j][0], a3, wA3.x);
                ffma2(acc[j][1], a3, wA3.y);
                ffma2(acc[j][2], a3, wB3.x);
                ffma2(acc[j][3], a3, wB3.y);
            }
        }

        // rows 0-3 of k fully consumed -> recycle regs with next-k gather
        xc[0] = __ldcg(reinterpret_cast<const float4*>(x + (size_t)ia.x * 16) + m);
        xc[1] = __ldcg(reinterpret_cast<const float4*>(x + (size_t)ia.y * 16) + m);
        xc[2] = __ldcg(reinterpret_cast<const float4*>(x + (size_t)ia.z * 16) + m);
        xc[3] = __ldcg(reinterpret_cast<const float4*>(x + (size_t)ia.w * 16) + m);

        // idx for next-k rows 4-7
        int4 ib = *reinterpret_cast<const int4*>(idxT + kn * NPB + nlb + 4);

        // phase 3: rows 4-7 x channels jj=0,1 (reload jj01 quads)
        {
            ulonglong2 wA0 = *reinterpret_cast<const ulonglong2*>(wk);
            ulonglong2 wB0 = *reinterpret_cast<const ulonglong2*>(wk + 32);
            ulonglong2 wA1 = *reinterpret_cast<const ulonglong2*>(wk + 64);
            ulonglong2 wB1 = *reinterpret_cast<const ulonglong2*>(wk + 96);
#pragma unroll
            for (int j = 4; j < 8; ++j) {
                const ull a0 = splat2(getf(xc[j], 0));
                ffma2(acc[j][0], a0, wA0.x);
                ffma2(acc[j][1], a0, wA0.y);
                ffma2(acc[j][2], a0, wB0.x);
                ffma2(acc[j][3], a0, wB0.y);
                const ull a1 = splat2(getf(xc[j], 1));
                ffma2(acc[j][0], a1, wA1.x);
                ffma2(acc[j][1], a1, wA1.y);
                ffma2(acc[j][2], a1, wB1.x);
                ffma2(acc[j][3], a1, wB1.y);
            }
        }
        // phase 4: rows 4-7 x channels jj=2,3 (reload wA2/wB2; wA3/wB3 live)
        {
            ulonglong2 wA2 = *reinterpret_cast<const ulonglong2*>(wk + 128);
            ulonglong2 wB2 = *reinterpret_cast<const ulonglong2*>(wk + 160);
#pragma unroll
            for (int j = 4; j < 8; ++j) {
                const ull a2 = splat2(getf(xc[j], 2));
                ffma2(acc[j][0], a2, wA2.x);
                ffma2(acc[j][1], a2, wA2.y);
                ffma2(acc[j][2], a2, wB2.x);
                ffma2(acc[j][3], a2, wB2.y);
                const ull a3 = splat2(getf(xc[j], 3));
                ffma2(acc[j][0], a3, wA3.x);
                ffma2(acc[j][1], a3, wA3.y);
                ffma2(acc[j][2], a3, wB3.x);
                ffma2(acc[j][3], a3, wB3.y);
            }
        }

        // rows 4-7 consumed -> recycle with next-k gather
        xc[4] = __ldcg(reinterpret_cast<const float4*>(x + (size_t)ib.x * 16) + m);
        xc[5] = __ldcg(reinterpret_cast<const float4*>(x + (size_t)ib.y * 16) + m);
        xc[6] = __ldcg(reinterpret_cast<const float4*>(x + (size_t)ib.z * 16) + m);
        xc[7] = __ldcg(reinterpret_cast<const float4*>(x + (size_t)ib.w * 16) + m);
    }

    // Epilogue: reduce channel-quad partials over the 4 m-lanes, add bias.
    float4 b0 = __ldg(reinterpret_cast<const float4*>(bias) + 2 * h);
    float4 b1 = __ldg(reinterpret_cast<const float4*>(bias) + 2 * h + 1);
    ull bp[4] = { pack2(b0.x, b0.y), pack2(b0.z, b0.w),
                  pack2(b1.x, b1.y), pack2(b1.z, b1.w) };

#pragma unroll
    for (int j = 0; j < 8; ++j) {
#pragma unroll
        for (int p = 0; p < 4; ++p) {
            ull v = acc[j][p];
            v = addp2(v, __shfl_xor_sync(0xffffffffu, v, 1));
            v = addp2(v, __shfl_xor_sync(0xffffffffu, v, 2));
            acc[j][p] = v;
        }
        const int node = warpbase + ns * 8 + j;
        if (m == 0 && node < n_out) {
            ulonglong2* op = reinterpret_cast<ulonglong2*>(
                out + (long long)node * 16 + 8 * h);
            ulonglong2 s0; s0.x = addp2(acc[j][0], bp[0]);
                           s0.y = addp2(acc[j][1], bp[1]);
            ulonglong2 s1; s1.x = addp2(acc[j][2], bp[2]);
                           s1.y = addp2(acc[j][3], bp[3]);
            op[0] = s0;
            op[1] = s1;
        }
    }
}

extern "C" void kernel_launch(void* const* d_in, const int* in_sizes, int n_in,
                              void* d_out, int out_size)
{
    const float* x    = (const float*)d_in[0];
    const float* w    = (const float*)d_in[1];
    const float* bias = (const float*)d_in[2];
    const int*   nbr  = (const int*)d_in[3];
    const int*   lvl  = (n_in > 4) ? (const int*)d_in[4] : nullptr;

    const int n_out = in_sizes[3] / KK;
    float* out = (float*)d_out;

    const long long conv_elems = (long long)n_out * 16;
    long long tail_start = conv_elems;
    int tail_count = 0;
    if ((long long)out_size > conv_elems && lvl != nullptr)
        tail_count = (int)((long long)out_size - conv_elems);

    const int grid = (n_out + NPB - 1) / NPB;
    conv_kernel<<<grid, TPB>>>(x, w, bias, nbr, out, n_out,
                               lvl, tail_start, tail_count);
}